// round 16
// baseline (speedup 1.0000x reference)
#include <cuda_runtime.h>

// SC-based GEMM, collapsed analytically:
//   out[m,n] = sum_k min(t1[m,k], t2[k,n]) * e1[m,k] * e2[k,n]
// t = floor(norm*256), e = sign * 2^{-s} (extra /256 folded into e2).
// Valid because rngSeq = arange(L) and the reference's ascending sequence
// are sorted unary prefixes, so popcount(b1 & b2) == min(t1, t2).
//
// Warp-autonomous split-K: each of 16 warps encodes ITS OWN k-slice of A
// and B into smem (no cross-warp barrier — only __syncwarp), then runs its
// mainloop on that slice. Warps overlap each other's cold-load latency.
// Barriers appear only around the final cross-warp partial reduction.
// 128 CTAs x 512 threads, one wave; packed f32x2 inner math.

#define MKN 256
#define TM 32            // tile rows (m)
#define TN 16            // tile cols (n)
#define NW 16            // warps per CTA
#define KW 16            // k per warp (256 / NW)

#define OFF_AE 8192
#define OFF_BT 16384
#define OFF_BE 20480
#define SMEM_FLOATS 24576   // 96KB

typedef unsigned long long u64;

__device__ __forceinline__ float2 sc_encode(float x, int extra_shift) {
    int xb   = __float_as_int(x);
    int bits = xb & 0x7FFFFFFF;               // |x| bits
    int q    = (bits >> 23) - 126;            // frexp exponent (normals)
    int s    = ((bits & 0x7FFFFF) == 0) ? (1 - q) : (-q);  // floor(-log2|x|)
    s = max(0, min(s, 8));                    // clip to DATA_WIDTH
    // thr = floor(|x| * 2^(s+8)); power-of-2 scale is exact.
    float thr = floorf(__int_as_float(bits) *
                       __int_as_float((127 + s + 8) << 23));
    // e = sign(x) * 2^{-s-extra}: built directly from bits.
    float e = __int_as_float(((127 - s - extra_shift) << 23) |
                             (xb & 0x80000000u));
    return make_float2(thr, e);
}

// acc_pair += min(at, {bt0,bt1}) * {ae,ae} * {be0,be1}   (packed f32x2)
__device__ __forceinline__ void sc_pair(u64& acc, float at, float bt0,
                                        float bt1, u64 aed, u64 bed) {
    asm("{\n\t"
        ".reg .f32 lo, hi;\n\t"
        ".reg .b64 p;\n\t"
        "min.f32 lo, %1, %2;\n\t"
        "min.f32 hi, %1, %3;\n\t"
        "mov.b64 p, {lo, hi};\n\t"
        "mul.rn.f32x2 p, p, %4;\n\t"
        "fma.rn.f32x2 %0, p, %5, %0;\n\t"
        "}"
        : "+l"(acc)
        : "f"(at), "f"(bt0), "f"(bt1), "l"(aed), "l"(bed));
}

__global__ __launch_bounds__(512, 1)
void sc_gemm_kernel(const float* __restrict__ A,
                    const float* __restrict__ B,
                    float* __restrict__ out) {
    extern __shared__ float smem[];
    float* sAt = smem;                        // [k][m], row 32 floats
    float* sAe = smem + OFF_AE;
    float* sBt = smem + OFF_BT;               // [k][n], row 16 floats
    float* sBe = smem + OFF_BE;
    float* sPart = smem;                      // tail overlay (16*512 floats)

    const int t    = threadIdx.x;
    const int lane = t & 31;
    const int w    = t >> 5;                  // warp id 0..15
    const int tn   = lane & 3;                // n-group (0..3)
    const int tm   = lane >> 2;               // m-group (0..7)
    const int m0   = blockIdx.y * TM;
    const int n0   = blockIdx.x * TN;
    const int kb   = w * KW;                  // this warp's k-slice

    // ---- Encode THIS WARP's A slice [32 m x 16 k] -> sAt/sAe[k][m].
    // lane = m; 16 consecutive k per thread; transposed STS is 32
    // consecutive floats per k (conflict-free).
    {
        const float* src = A + (m0 + lane) * MKN + kb;
        #pragma unroll
        for (int v = 0; v < 4; ++v) {
            float4 x = *(const float4*)(src + v * 4);
            float xs[4] = {x.x, x.y, x.z, x.w};
            #pragma unroll
            for (int j = 0; j < 4; ++j) {
                float2 en = sc_encode(xs[j], 0);
                int k = kb + v * 4 + j;
                sAt[k * TM + lane] = en.x;
                sAe[k * TM + lane] = en.y;
            }
        }
    }
    // ---- Encode THIS WARP's B slice [16 k x 16 n] -> sBt/sBe[k][n].
    // lane pair covers one k-row: k = kb + lane/2, n-half = (lane&1)*8.
    {
        int k  = kb + (lane >> 1);
        int nh = (lane & 1) * 8;
        const float* src = B + k * MKN + n0 + nh;
        float4 x0 = *(const float4*)src;
        float4 x1 = *(const float4*)(src + 4);
        float2 e0 = sc_encode(x0.x, 8), e1 = sc_encode(x0.y, 8);
        float2 e2 = sc_encode(x0.z, 8), e3 = sc_encode(x0.w, 8);
        float2 e4 = sc_encode(x1.x, 8), e5 = sc_encode(x1.y, 8);
        float2 e6 = sc_encode(x1.z, 8), e7 = sc_encode(x1.w, 8);
        *(float4*)&sBt[k * TN + nh]     = make_float4(e0.x, e1.x, e2.x, e3.x);
        *(float4*)&sBt[k * TN + nh + 4] = make_float4(e4.x, e5.x, e6.x, e7.x);
        *(float4*)&sBe[k * TN + nh]     = make_float4(e0.y, e1.y, e2.y, e3.y);
        *(float4*)&sBe[k * TN + nh + 4] = make_float4(e4.y, e5.y, e6.y, e7.y);
    }
    __syncwarp();                             // slice visible within the warp

    // ---- Mainloop on own k-slice; 4x4 per thread, packed f32x2.
    u64 acc01[4] = {0ull, 0ull, 0ull, 0ull};  // (j0,j1) pairs per i
    u64 acc23[4] = {0ull, 0ull, 0ull, 0ull};  // (j2,j3) pairs per i

    #pragma unroll
    for (int kk = 0; kk < KW; ++kk) {
        int k = kb + kk;
        float4 at = *(const float4*)&sAt[k * TM + tm * 4];
        float4 ae = *(const float4*)&sAe[k * TM + tm * 4];
        float4 bt = *(const float4*)&sBt[k * TN + tn * 4];
        ulonglong2 be = *(const ulonglong2*)&sBe[k * TN + tn * 4];
        const float* atp = &at.x; const float* aep = &ae.x;
        u64 aed[4];
        #pragma unroll
        for (int i = 0; i < 4; ++i)
            asm("mov.b64 %0, {%1, %1};" : "=l"(aed[i]) : "f"(aep[i]));
        #pragma unroll
        for (int i = 0; i < 4; ++i) {
            sc_pair(acc01[i], atp[i], bt.x, bt.y, aed[i], be.x);
            sc_pair(acc23[i], atp[i], bt.z, bt.w, aed[i], be.y);
        }
    }

    // ---- Cross-warp reduction via smem overlay on the A region.
    __syncthreads();                          // all warps done with smem
    #pragma unroll
    for (int i = 0; i < 4; ++i) {
        float f0, f1, f2, f3;
        asm("mov.b64 {%0, %1}, %2;" : "=f"(f0), "=f"(f1) : "l"(acc01[i]));
        asm("mov.b64 {%0, %1}, %2;" : "=f"(f2), "=f"(f3) : "l"(acc23[i]));
        *(float4*)&sPart[w * 512 + (tm * 4 + i) * TN + tn * 4] =
            make_float4(f0, f1, f2, f3);
    }
    __syncthreads();

    // One output per thread; fixed warp order -> deterministic.
    {
        float s0 = 0.0f, s1 = 0.0f, s2 = 0.0f, s3 = 0.0f;
        #pragma unroll
        for (int r = 0; r < NW; r += 4) {
            s0 += sPart[(r + 0) * 512 + t];
            s1 += sPart[(r + 1) * 512 + t];
            s2 += sPart[(r + 2) * 512 + t];
            s3 += sPart[(r + 3) * 512 + t];
        }
        int mloc = t >> 4;                    // 0..31
        int nloc = t & 15;                    // 0..15
        out[(m0 + mloc) * MKN + n0 + nloc] = (s0 + s1) + (s2 + s3);
    }
}

extern "C" void kernel_launch(void* const* d_in, const int* in_sizes, int n_in,
                              void* d_out, int out_size) {
    const float* A = (const float*)d_in[0];   // tensor_1 [256,256]
    const float* B = (const float*)d_in[1];   // tensor_2 [256,256]
    // d_in[2] = rngSeq (arange(256)); sortedness folded into the math.
    float* out = (float*)d_out;

    static int configured = 0;                // idempotent attr set
    if (!configured) {
        cudaFuncSetAttribute(sc_gemm_kernel,
                             cudaFuncAttributeMaxDynamicSharedMemorySize,
                             SMEM_FLOATS * 4);
        configured = 1;
    }

    dim3 grid(MKN / TN, MKN / TM);            // 16 x 8 = 128 CTAs, one wave
    sc_gemm_kernel<<<grid, 512, SMEM_FLOATS * 4>>>(A, B, out);
}